// round 6
// baseline (speedup 1.0000x reference)
#include <cuda_runtime.h>
#include <math.h>

#define BATCH      262144
#define IN_DIM     96
#define HID        32
#define D          16
#define K_OTHERS   15
#define N_FOOD     16
#define LN_EPS     1e-5f
#define ATT_SCALE  0.25f        // 1/sqrt(16)

#define TPB        128

typedef unsigned long long u64;

// ---------------- packed f32x2 helpers (sm_100+ PTX) ----------------
__device__ __forceinline__ u64 pack2(float lo, float hi) {
    u64 r;
    asm("mov.b64 %0, {%1, %2};" : "=l"(r) : "f"(lo), "f"(hi));
    return r;
}
__device__ __forceinline__ void unpack2(u64 v, float& lo, float& hi) {
    asm("mov.b64 {%0, %1}, %2;" : "=f"(lo), "=f"(hi) : "l"(v));
}
__device__ __forceinline__ u64 fma2(u64 a, u64 b, u64 c) {
    u64 d;
    asm("fma.rn.f32x2 %0, %1, %2, %3;" : "=l"(d) : "l"(a), "l"(b), "l"(c));
    return d;
}
__device__ __forceinline__ u64 mul2(u64 a, u64 b) {
    u64 d;
    asm("mul.rn.f32x2 %0, %1, %2;" : "=l"(d) : "l"(a), "l"(b));
    return d;
}
__device__ __forceinline__ u64 relu2(u64 v) {
    float a, b;
    unpack2(v, a, b);
    return pack2(fmaxf(a, 0.f), fmaxf(b, 0.f));
}

// ---- shared-memory weight layout (float offsets, all 16B aligned) ----
#define ENW1 0      // 128  (4 x 32)
#define ENB1 128    // 32
#define ENW2 160    // 512  (32 x 16)
#define ENB2 672    // 16
#define OAW1 688    // 128
#define OAB1 816    // 32
#define OAW2 848    // 512
#define OAB2 1360   // 16
#define GW1  1376   // 64   (2 x 32)
#define GB1  1440   // 32
#define GW2  1472   // 512
#define GB2  1984   // 16
#define OLNG 2000   // 16
#define OLNB 2016   // 16
#define GLNG 2032   // 16
#define GLNB 2048   // 16
#define AW1  2064   // 1536 (48 x 32)
#define AB1  3600   // 32
#define AW2  3632   // 1024 (32 x 32)
#define AB2  4656   // 32
#define AW3  4688   // 64   (32 x 2)
#define AB3  4752   // 2 (+pad)
#define SW_TOTAL 4768

__device__ __forceinline__ void cpyw(float* dst, const float* __restrict__ src,
                                     int n, int tid) {
    for (int i = tid; i < n; i += TPB) dst[i] = src[i];
}

// x[IN] -> relu(x@W1+b1) (32) -> relu(h@W2+b2) -> out8 = 8 packed f32x2.
// Register-lean: layer-1 activations stay PACKED; ReLU + broadcast unpack
// happens lazily per pair inside the layer-2 loop (no hs[32] scalar array).
template <int IN>
__device__ __forceinline__ void encode2(const float* __restrict__ x,
                                        const float* __restrict__ W1,
                                        const float* __restrict__ b1,
                                        const float* __restrict__ W2,
                                        const float* __restrict__ b2,
                                        u64* __restrict__ out8) {
    u64 h[16];
    {
        const u64* bv = (const u64*)b1;
        #pragma unroll
        for (int j = 0; j < 16; j++) h[j] = bv[j];
    }
    #pragma unroll
    for (int i = 0; i < IN; i++) {
        u64 xx = pack2(x[i], x[i]);
        const ulonglong2* wv = (const ulonglong2*)(W1 + i * HID);
        #pragma unroll
        for (int j = 0; j < 8; j++) {
            ulonglong2 w = wv[j];
            h[2*j+0] = fma2(xx, w.x, h[2*j+0]);
            h[2*j+1] = fma2(xx, w.y, h[2*j+1]);
        }
    }
    u64 o[8];
    {
        const u64* bv = (const u64*)b2;
        #pragma unroll
        for (int d = 0; d < 8; d++) o[d] = bv[d];
    }
    // layer 2: consume packed h pair-by-pair (lazy relu+unpack)
    #pragma unroll
    for (int j2 = 0; j2 < 16; j2++) {
        float a, b;
        unpack2(h[j2], a, b);
        a = fmaxf(a, 0.f);
        b = fmaxf(b, 0.f);
        u64 ha = pack2(a, a);
        const ulonglong2* wa = (const ulonglong2*)(W2 + (2*j2+0) * D);
        #pragma unroll
        for (int d = 0; d < 4; d++) {
            ulonglong2 w = wa[d];
            o[2*d+0] = fma2(ha, w.x, o[2*d+0]);
            o[2*d+1] = fma2(ha, w.y, o[2*d+1]);
        }
        u64 hb = pack2(b, b);
        const ulonglong2* wb = (const ulonglong2*)(W2 + (2*j2+1) * D);
        #pragma unroll
        for (int d = 0; d < 4; d++) {
            ulonglong2 w = wb[d];
            o[2*d+0] = fma2(hb, w.x, o[2*d+0]);
            o[2*d+1] = fma2(hb, w.y, o[2*d+1]);
        }
    }
    #pragma unroll
    for (int d = 0; d < 8; d++) out8[d] = relu2(o[d]);
}

// acc8 (packed weighted sums) * inv -> LayerNorm -> relu -> packed y8
__device__ __forceinline__ void ln_relu_packed(const u64* __restrict__ acc8,
                                               float inv,
                                               const float* __restrict__ g,
                                               const float* __restrict__ b,
                                               u64* __restrict__ y8) {
    float xv[D];
    #pragma unroll
    for (int d = 0; d < 8; d++) {
        float a, bb;
        unpack2(acc8[d], a, bb);
        xv[2*d+0] = a * inv;
        xv[2*d+1] = bb * inv;
    }
    float s = 0.f;
    #pragma unroll
    for (int d = 0; d < D; d++) s += xv[d];
    float mu = s * (1.f / D);
    float v = 0.f;
    #pragma unroll
    for (int d = 0; d < D; d++) { float c = xv[d] - mu; v = fmaf(c, c, v); }
    float is = rsqrtf(v * (1.f / D) + LN_EPS);
    #pragma unroll
    for (int d = 0; d < 8; d++) {
        float ya = fmaxf(fmaf((xv[2*d+0] - mu) * is, g[2*d+0], b[2*d+0]), 0.f);
        float yb = fmaxf(fmaf((xv[2*d+1] - mu) * is, g[2*d+1], b[2*d+1]), 0.f);
        y8[d] = pack2(ya, yb);
    }
}

// online-softmax attention step over one encoded agent; updates (m, ss, acc8)
__device__ __forceinline__ void attend_step(const u64* __restrict__ e8,
                                            const u64* __restrict__ self8,
                                            float& m, float& ss,
                                            u64* __restrict__ acc8) {
    u64 d2 = mul2(self8[0], e8[0]);
    #pragma unroll
    for (int d = 1; d < 8; d++) d2 = fma2(self8[d], e8[d], d2);
    float sa, sb;
    unpack2(d2, sa, sb);
    float sc = (sa + sb) * ATT_SCALE;

    float nm   = fmaxf(m, sc);
    float corr = __expf(m - nm);   // first iter: exp(-inf)=0
    float w    = __expf(sc - nm);
    ss = fmaf(ss, corr, w);
    u64 c2 = pack2(corr, corr);
    u64 w2 = pack2(w, w);
    #pragma unroll
    for (int d = 0; d < 8; d++)
        acc8[d] = fma2(acc8[d], c2, mul2(w2, e8[d]));
    m = nm;
}

// packed 16-dim segment -> head layer-1 accumulators h[16] (packed)
__device__ __forceinline__ void head_seg(const u64* __restrict__ x8,
                                         const float* __restrict__ W,  // 16 x 32
                                         u64* __restrict__ h) {
    #pragma unroll
    for (int i2 = 0; i2 < 8; i2++) {
        float a, b;
        unpack2(x8[i2], a, b);
        u64 xa = pack2(a, a);
        const ulonglong2* wa = (const ulonglong2*)(W + (2*i2+0) * HID);
        #pragma unroll
        for (int j = 0; j < 8; j++) {
            ulonglong2 w = wa[j];
            h[2*j+0] = fma2(xa, w.x, h[2*j+0]);
            h[2*j+1] = fma2(xa, w.y, h[2*j+1]);
        }
        u64 xb = pack2(b, b);
        const ulonglong2* wb = (const ulonglong2*)(W + (2*i2+1) * HID);
        #pragma unroll
        for (int j = 0; j < 8; j++) {
            ulonglong2 w = wb[j];
            h[2*j+0] = fma2(xb, w.x, h[2*j+0]);
            h[2*j+1] = fma2(xb, w.y, h[2*j+1]);
        }
    }
}

__global__ void __launch_bounds__(TPB, 3)
actor_kernel(const float* __restrict__ s,
             const float* __restrict__ enW1, const float* __restrict__ enb1,
             const float* __restrict__ enW2, const float* __restrict__ enb2,
             const float* __restrict__ oaW1, const float* __restrict__ oab1,
             const float* __restrict__ oaW2, const float* __restrict__ oab2,
             const float* __restrict__ gW1,  const float* __restrict__ gb1,
             const float* __restrict__ gW2,  const float* __restrict__ gb2,
             const float* __restrict__ olng, const float* __restrict__ olnb,
             const float* __restrict__ glng, const float* __restrict__ glnb,
             const float* __restrict__ aW1,  const float* __restrict__ ab1,
             const float* __restrict__ aW2,  const float* __restrict__ ab2,
             const float* __restrict__ aW3,  const float* __restrict__ ab3,
             float* __restrict__ out) {
    __shared__ float sw[SW_TOTAL];
    const int tid = threadIdx.x;

    cpyw(sw + ENW1, enW1, 128, tid);  cpyw(sw + ENB1, enb1, 32, tid);
    cpyw(sw + ENW2, enW2, 512, tid);  cpyw(sw + ENB2, enb2, 16, tid);
    cpyw(sw + OAW1, oaW1, 128, tid);  cpyw(sw + OAB1, oab1, 32, tid);
    cpyw(sw + OAW2, oaW2, 512, tid);  cpyw(sw + OAB2, oab2, 16, tid);
    cpyw(sw + GW1,  gW1,  64,  tid);  cpyw(sw + GB1,  gb1,  32, tid);
    cpyw(sw + GW2,  gW2,  512, tid);  cpyw(sw + GB2,  gb2,  16, tid);
    cpyw(sw + OLNG, olng, 16,  tid);  cpyw(sw + OLNB, olnb, 16, tid);
    cpyw(sw + GLNG, glng, 16,  tid);  cpyw(sw + GLNB, glnb, 16, tid);
    cpyw(sw + AW1,  aW1,  1536, tid); cpyw(sw + AB1,  ab1,  32, tid);
    cpyw(sw + AW2,  aW2,  1024, tid); cpyw(sw + AB2,  ab2,  32, tid);
    cpyw(sw + AW3,  aW3,  64,  tid);  cpyw(sw + AB3,  ab3,  2,  tid);
    __syncthreads();

    const int r = blockIdx.x * TPB + tid;
    const float* __restrict__ row = s + (size_t)r * IN_DIM;

    // ---------------- self encoder ----------------
    u64 self8[8];
    {
        float4 x4 = *(const float4*)row;
        float xin[4] = {x4.x, x4.y, x4.z, x4.w};
        encode2<4>(xin, sw + ENW1, sw + ENB1, sw + ENW2, sw + ENB2, self8);
    }

    // ---------------- other-agent attention (online softmax) ----------------
    u64 other8[8];
    {
        u64 acc8[8];
        #pragma unroll
        for (int d = 0; d < 8; d++) acc8[d] = 0ull;   // packed (0,0)
        float m = -INFINITY, ss = 0.f;
        #pragma unroll 1        // keep body rolled (I$)
        for (int k = 0; k < K_OTHERS; k++) {
            float2 a = *(const float2*)(row + 4 + 2 * k);
            float2 b = *(const float2*)(row + 4 + 2 * K_OTHERS + 2 * k);
            float xin[4] = {a.x, a.y, b.x, b.y};
            u64 e8[8];
            encode2<4>(xin, sw + OAW1, sw + OAB1, sw + OAW2, sw + OAB2, e8);
            attend_step(e8, self8, m, ss, acc8);
        }
        ln_relu_packed(acc8, 1.f / ss, sw + OLNG, sw + OLNB, other8);
    }

    // ---------------- food attention ----------------
    u64 food8[8];
    {
        u64 acc8[8];
        #pragma unroll
        for (int d = 0; d < 8; d++) acc8[d] = 0ull;
        float m = -INFINITY, ss = 0.f;
        #pragma unroll 1        // keep body rolled (I$)
        for (int k = 0; k < N_FOOD; k++) {
            float2 a = *(const float2*)(row + IN_DIM - 2 * N_FOOD + 2 * k);
            float xin[2] = {a.x, a.y};
            u64 e8[8];
            encode2<2>(xin, sw + GW1, sw + GB1, sw + GW2, sw + GB2, e8);
            attend_step(e8, self8, m, ss, acc8);
        }
        ln_relu_packed(acc8, 1.f / ss, sw + GLNG, sw + GLNB, food8);
    }

    // ---------------- actor head: merged = [self, food, other] ----------------
    u64 h1[16];   // packed layer-1 accumulators
    {
        const u64* bv = (const u64*)(sw + AB1);
        #pragma unroll
        for (int j = 0; j < 16; j++) h1[j] = bv[j];
        head_seg(self8, sw + AW1,             h1);
        head_seg(food8, sw + AW1 + D * HID,   h1);
        head_seg(other8, sw + AW1 + 2*D*HID,  h1);
    }

    u64 h2[16];   // packed layer-2 accumulators
    {
        const u64* bv = (const u64*)(sw + AB2);
        #pragma unroll
        for (int j = 0; j < 16; j++) h2[j] = bv[j];
        // consume h1 pair-by-pair with lazy leaky-relu
        #pragma unroll
        for (int i2 = 0; i2 < 16; i2++) {
            float a, b;
            unpack2(h1[i2], a, b);
            a = (a > 0.f) ? a : 0.01f * a;
            b = (b > 0.f) ? b : 0.01f * b;
            u64 xa = pack2(a, a);
            const ulonglong2* wa = (const ulonglong2*)(sw + AW2 + (2*i2+0) * HID);
            #pragma unroll
            for (int j = 0; j < 8; j++) {
                ulonglong2 w = wa[j];
                h2[2*j+0] = fma2(xa, w.x, h2[2*j+0]);
                h2[2*j+1] = fma2(xa, w.y, h2[2*j+1]);
            }
            u64 xb = pack2(b, b);
            const ulonglong2* wb = (const ulonglong2*)(sw + AW2 + (2*i2+1) * HID);
            #pragma unroll
            for (int j = 0; j < 8; j++) {
                ulonglong2 w = wb[j];
                h2[2*j+0] = fma2(xb, w.x, h2[2*j+0]);
                h2[2*j+1] = fma2(xb, w.y, h2[2*j+1]);
            }
        }
    }

    // final 32 -> 2: rows of AW3 are (w0, w1) pairs -> packed accumulate
    u64 o2 = *(const u64*)(sw + AB3);
    {
        const u64* wv = (const u64*)(sw + AW3);
        #pragma unroll
        for (int i2 = 0; i2 < 16; i2++) {
            float a, b;
            unpack2(h2[i2], a, b);
            a = (a > 0.f) ? a : 0.01f * a;
            b = (b > 0.f) ? b : 0.01f * b;
            o2 = fma2(pack2(a, a), wv[2*i2+0], o2);
            o2 = fma2(pack2(b, b), wv[2*i2+1], o2);
        }
    }
    float o0, o1;
    unpack2(o2, o0, o1);

    float2 res;
    res.x = tanhf(o0);   // exact libm tanh (precision safety, 2/thread)
    res.y = tanhf(o1);
    *(float2*)(out + (size_t)2 * r) = res;
}

extern "C" void kernel_launch(void* const* d_in, const int* in_sizes, int n_in,
                              void* d_out, int out_size) {
    (void)in_sizes; (void)n_in; (void)out_size;
    actor_kernel<<<BATCH / TPB, TPB>>>(
        (const float*)d_in[0],
        (const float*)d_in[1],  (const float*)d_in[2],
        (const float*)d_in[3],  (const float*)d_in[4],
        (const float*)d_in[5],  (const float*)d_in[6],
        (const float*)d_in[7],  (const float*)d_in[8],
        (const float*)d_in[9],  (const float*)d_in[10],
        (const float*)d_in[11], (const float*)d_in[12],
        (const float*)d_in[13], (const float*)d_in[14],
        (const float*)d_in[15], (const float*)d_in[16],
        (const float*)d_in[17], (const float*)d_in[18],
        (const float*)d_in[19], (const float*)d_in[20],
        (const float*)d_in[21], (const float*)d_in[22],
        (float*)d_out);
}

// round 7
// speedup vs baseline: 1.3110x; 1.3110x over previous
#include <cuda_runtime.h>
#include <math.h>

#define BATCH      262144
#define IN_DIM     96
#define HID        32
#define D          16
#define K_OTHERS   15
#define N_FOOD     16
#define LN_EPS     1e-5f
#define ATT_SCALE  0.25f        // 1/sqrt(16)

#define TPB        128

typedef unsigned long long u64;

// ---------------- global scratch (static device arrays; no allocation) ----
__device__ u64 g_self [BATCH * D / 2];   // 16 floats/row stored as 8 u64
__device__ u64 g_other[BATCH * D / 2];
__device__ u64 g_food [BATCH * D / 2];

// ---------------- packed f32x2 helpers (sm_100+ PTX) ----------------
__device__ __forceinline__ u64 pack2(float lo, float hi) {
    u64 r;
    asm("mov.b64 %0, {%1, %2};" : "=l"(r) : "f"(lo), "f"(hi));
    return r;
}
__device__ __forceinline__ void unpack2(u64 v, float& lo, float& hi) {
    asm("mov.b64 {%0, %1}, %2;" : "=f"(lo), "=f"(hi) : "l"(v));
}
__device__ __forceinline__ u64 fma2(u64 a, u64 b, u64 c) {
    u64 d;
    asm("fma.rn.f32x2 %0, %1, %2, %3;" : "=l"(d) : "l"(a), "l"(b), "l"(c));
    return d;
}
__device__ __forceinline__ u64 mul2(u64 a, u64 b) {
    u64 d;
    asm("mul.rn.f32x2 %0, %1, %2;" : "=l"(d) : "l"(a), "l"(b));
    return d;
}
__device__ __forceinline__ u64 relu2(u64 v) {
    float a, b;
    unpack2(v, a, b);
    return pack2(fmaxf(a, 0.f), fmaxf(b, 0.f));
}

__device__ __forceinline__ void cpyw(float* dst, const float* __restrict__ src,
                                     int n, int tid) {
    for (int i = tid; i < n; i += TPB) dst[i] = src[i];
}

// x[IN] -> relu(x@W1+b1) (32) -> relu(h@W2+b2) -> out8 = 8 packed f32x2.
// Layer-1 activations stay packed; lazy relu+unpack in layer-2 loop.
template <int IN>
__device__ __forceinline__ void encode2(const float* __restrict__ x,
                                        const float* __restrict__ W1,
                                        const float* __restrict__ b1,
                                        const float* __restrict__ W2,
                                        const float* __restrict__ b2,
                                        u64* __restrict__ out8) {
    u64 h[16];
    {
        const u64* bv = (const u64*)b1;
        #pragma unroll
        for (int j = 0; j < 16; j++) h[j] = bv[j];
    }
    #pragma unroll
    for (int i = 0; i < IN; i++) {
        u64 xx = pack2(x[i], x[i]);
        const ulonglong2* wv = (const ulonglong2*)(W1 + i * HID);
        #pragma unroll
        for (int j = 0; j < 8; j++) {
            ulonglong2 w = wv[j];
            h[2*j+0] = fma2(xx, w.x, h[2*j+0]);
            h[2*j+1] = fma2(xx, w.y, h[2*j+1]);
        }
    }
    u64 o[8];
    {
        const u64* bv = (const u64*)b2;
        #pragma unroll
        for (int d = 0; d < 8; d++) o[d] = bv[d];
    }
    #pragma unroll
    for (int j2 = 0; j2 < 16; j2++) {
        float a, b;
        unpack2(h[j2], a, b);
        a = fmaxf(a, 0.f);
        b = fmaxf(b, 0.f);
        u64 ha = pack2(a, a);
        const ulonglong2* wa = (const ulonglong2*)(W2 + (2*j2+0) * D);
        #pragma unroll
        for (int d = 0; d < 4; d++) {
            ulonglong2 w = wa[d];
            o[2*d+0] = fma2(ha, w.x, o[2*d+0]);
            o[2*d+1] = fma2(ha, w.y, o[2*d+1]);
        }
        u64 hb = pack2(b, b);
        const ulonglong2* wb = (const ulonglong2*)(W2 + (2*j2+1) * D);
        #pragma unroll
        for (int d = 0; d < 4; d++) {
            ulonglong2 w = wb[d];
            o[2*d+0] = fma2(hb, w.x, o[2*d+0]);
            o[2*d+1] = fma2(hb, w.y, o[2*d+1]);
        }
    }
    #pragma unroll
    for (int d = 0; d < 8; d++) out8[d] = relu2(o[d]);
}

// acc8 * inv -> LayerNorm -> relu -> packed y8
__device__ __forceinline__ void ln_relu_packed(const u64* __restrict__ acc8,
                                               float inv,
                                               const float* __restrict__ g,
                                               const float* __restrict__ b,
                                               u64* __restrict__ y8) {
    float xv[D];
    #pragma unroll
    for (int d = 0; d < 8; d++) {
        float a, bb;
        unpack2(acc8[d], a, bb);
        xv[2*d+0] = a * inv;
        xv[2*d+1] = bb * inv;
    }
    float s = 0.f;
    #pragma unroll
    for (int d = 0; d < D; d++) s += xv[d];
    float mu = s * (1.f / D);
    float v = 0.f;
    #pragma unroll
    for (int d = 0; d < D; d++) { float c = xv[d] - mu; v = fmaf(c, c, v); }
    float is = rsqrtf(v * (1.f / D) + LN_EPS);
    #pragma unroll
    for (int d = 0; d < 8; d++) {
        float ya = fmaxf(fmaf((xv[2*d+0] - mu) * is, g[2*d+0], b[2*d+0]), 0.f);
        float yb = fmaxf(fmaf((xv[2*d+1] - mu) * is, g[2*d+1], b[2*d+1]), 0.f);
        y8[d] = pack2(ya, yb);
    }
}

// online-softmax step; updates (m, ss, acc8)
__device__ __forceinline__ void attend_step(const u64* __restrict__ e8,
                                            const u64* __restrict__ self8,
                                            float& m, float& ss,
                                            u64* __restrict__ acc8) {
    u64 d2 = mul2(self8[0], e8[0]);
    #pragma unroll
    for (int d = 1; d < 8; d++) d2 = fma2(self8[d], e8[d], d2);
    float sa, sb;
    unpack2(d2, sa, sb);
    float sc = (sa + sb) * ATT_SCALE;

    float nm   = fmaxf(m, sc);
    float corr = __expf(m - nm);   // first iter: exp(-inf)=0
    float w    = __expf(sc - nm);
    ss = fmaf(ss, corr, w);
    u64 c2 = pack2(corr, corr);
    u64 w2 = pack2(w, w);
    #pragma unroll
    for (int d = 0; d < 8; d++)
        acc8[d] = fma2(acc8[d], c2, mul2(w2, e8[d]));
    m = nm;
}

// packed 16-dim segment -> 32-wide packed accumulators h[16]
__device__ __forceinline__ void head_seg(const u64* __restrict__ x8,
                                         const float* __restrict__ W,  // 16 x 32
                                         u64* __restrict__ h) {
    #pragma unroll
    for (int i2 = 0; i2 < 8; i2++) {
        float a, b;
        unpack2(x8[i2], a, b);
        u64 xa = pack2(a, a);
        const ulonglong2* wa = (const ulonglong2*)(W + (2*i2+0) * HID);
        #pragma unroll
        for (int j = 0; j < 8; j++) {
            ulonglong2 w = wa[j];
            h[2*j+0] = fma2(xa, w.x, h[2*j+0]);
            h[2*j+1] = fma2(xa, w.y, h[2*j+1]);
        }
        u64 xb = pack2(b, b);
        const ulonglong2* wb = (const ulonglong2*)(W + (2*i2+1) * HID);
        #pragma unroll
        for (int j = 0; j < 8; j++) {
            ulonglong2 w = wb[j];
            h[2*j+0] = fma2(xb, w.x, h[2*j+0]);
            h[2*j+1] = fma2(xb, w.y, h[2*j+1]);
        }
    }
}

// ===================== Kernel A: self encoder =====================
__global__ void __launch_bounds__(TPB)
k_self(const float* __restrict__ s,
       const float* __restrict__ enW1, const float* __restrict__ enb1,
       const float* __restrict__ enW2, const float* __restrict__ enb2) {
    __shared__ float sw[688];   // W1 128 | b1 32 @128 | W2 512 @160 | b2 16 @672
    const int tid = threadIdx.x;
    cpyw(sw, enW1, 128, tid);       cpyw(sw + 128, enb1, 32, tid);
    cpyw(sw + 160, enW2, 512, tid); cpyw(sw + 672, enb2, 16, tid);
    __syncthreads();

    const int r = blockIdx.x * TPB + tid;
    float4 x4 = *(const float4*)(s + (size_t)r * IN_DIM);
    float xin[4] = {x4.x, x4.y, x4.z, x4.w};
    u64 o8[8];
    encode2<4>(xin, sw, sw + 128, sw + 160, sw + 672, o8);
    ulonglong2* gp = (ulonglong2*)(g_self + (size_t)r * 8);
    #pragma unroll
    for (int d = 0; d < 4; d++) gp[d] = make_ulonglong2(o8[2*d], o8[2*d+1]);
}

// ===================== Kernel B: other-agent attention =====================
__global__ void __launch_bounds__(TPB)
k_other(const float* __restrict__ s,
        const float* __restrict__ oaW1, const float* __restrict__ oab1,
        const float* __restrict__ oaW2, const float* __restrict__ oab2,
        const float* __restrict__ olng, const float* __restrict__ olnb) {
    __shared__ float sw[720];  // W1 128 | b1 32 @128 | W2 512 @160 | b2 16 @672 | g 16 @688 | b 16 @704
    const int tid = threadIdx.x;
    cpyw(sw, oaW1, 128, tid);       cpyw(sw + 128, oab1, 32, tid);
    cpyw(sw + 160, oaW2, 512, tid); cpyw(sw + 672, oab2, 16, tid);
    cpyw(sw + 688, olng, 16, tid);  cpyw(sw + 704, olnb, 16, tid);
    __syncthreads();

    const int r = blockIdx.x * TPB + tid;
    const float* __restrict__ row = s + (size_t)r * IN_DIM;

    u64 self8[8];
    {
        const ulonglong2* gp = (const ulonglong2*)(g_self + (size_t)r * 8);
        #pragma unroll
        for (int d = 0; d < 4; d++) {
            ulonglong2 v = gp[d];
            self8[2*d] = v.x; self8[2*d+1] = v.y;
        }
    }

    u64 acc8[8];
    #pragma unroll
    for (int d = 0; d < 8; d++) acc8[d] = 0ull;
    float m = -INFINITY, ss = 0.f;
    #pragma unroll 1
    for (int k = 0; k < K_OTHERS; k++) {
        float2 a = *(const float2*)(row + 4 + 2 * k);
        float2 b = *(const float2*)(row + 4 + 2 * K_OTHERS + 2 * k);
        float xin[4] = {a.x, a.y, b.x, b.y};
        u64 e8[8];
        encode2<4>(xin, sw, sw + 128, sw + 160, sw + 672, e8);
        attend_step(e8, self8, m, ss, acc8);
    }
    u64 y8[8];
    ln_relu_packed(acc8, 1.f / ss, sw + 688, sw + 704, y8);
    ulonglong2* gp = (ulonglong2*)(g_other + (size_t)r * 8);
    #pragma unroll
    for (int d = 0; d < 4; d++) gp[d] = make_ulonglong2(y8[2*d], y8[2*d+1]);
}

// ===================== Kernel C: food attention =====================
__global__ void __launch_bounds__(TPB)
k_food(const float* __restrict__ s,
       const float* __restrict__ gW1, const float* __restrict__ gb1,
       const float* __restrict__ gW2, const float* __restrict__ gb2,
       const float* __restrict__ glng, const float* __restrict__ glnb) {
    __shared__ float sw[656];  // W1 64 | b1 32 @64 | W2 512 @96 | b2 16 @608 | g 16 @624 | b 16 @640
    const int tid = threadIdx.x;
    cpyw(sw, gW1, 64, tid);        cpyw(sw + 64, gb1, 32, tid);
    cpyw(sw + 96, gW2, 512, tid);  cpyw(sw + 608, gb2, 16, tid);
    cpyw(sw + 624, glng, 16, tid); cpyw(sw + 640, glnb, 16, tid);
    __syncthreads();

    const int r = blockIdx.x * TPB + tid;
    const float* __restrict__ row = s + (size_t)r * IN_DIM;

    u64 self8[8];
    {
        const ulonglong2* gp = (const ulonglong2*)(g_self + (size_t)r * 8);
        #pragma unroll
        for (int d = 0; d < 4; d++) {
            ulonglong2 v = gp[d];
            self8[2*d] = v.x; self8[2*d+1] = v.y;
        }
    }

    u64 acc8[8];
    #pragma unroll
    for (int d = 0; d < 8; d++) acc8[d] = 0ull;
    float m = -INFINITY, ss = 0.f;
    #pragma unroll 1
    for (int k = 0; k < N_FOOD; k++) {
        float2 a = *(const float2*)(row + IN_DIM - 2 * N_FOOD + 2 * k);
        float xin[2] = {a.x, a.y};
        u64 e8[8];
        encode2<2>(xin, sw, sw + 64, sw + 96, sw + 608, e8);
        attend_step(e8, self8, m, ss, acc8);
    }
    u64 y8[8];
    ln_relu_packed(acc8, 1.f / ss, sw + 624, sw + 640, y8);
    ulonglong2* gp = (ulonglong2*)(g_food + (size_t)r * 8);
    #pragma unroll
    for (int d = 0; d < 4; d++) gp[d] = make_ulonglong2(y8[2*d], y8[2*d+1]);
}

// ===================== Kernel D: actor head =====================
__global__ void __launch_bounds__(TPB)
k_head(const float* __restrict__ aW1, const float* __restrict__ ab1,
       const float* __restrict__ aW2, const float* __restrict__ ab2,
       const float* __restrict__ aW3, const float* __restrict__ ab3,
       float* __restrict__ out) {
    // AW1 1536 | AB1 32 @1536 | AW2 1024 @1568 | AB2 32 @2592 | AW3 64 @2624 | AB3 2 @2688
    __shared__ float sw[2692];
    const int tid = threadIdx.x;
    cpyw(sw, aW1, 1536, tid);        cpyw(sw + 1536, ab1, 32, tid);
    cpyw(sw + 1568, aW2, 1024, tid); cpyw(sw + 2592, ab2, 32, tid);
    cpyw(sw + 2624, aW3, 64, tid);   cpyw(sw + 2688, ab3, 2, tid);
    __syncthreads();

    const int r = blockIdx.x * TPB + tid;

    u64 h1[16];
    {
        const u64* bv = (const u64*)(sw + 1536);
        #pragma unroll
        for (int j = 0; j < 16; j++) h1[j] = bv[j];
    }
    // stream each segment: load 16 floats, accumulate, reuse regs
    {
        u64 x8[8];
        const ulonglong2* gp = (const ulonglong2*)(g_self + (size_t)r * 8);
        #pragma unroll
        for (int d = 0; d < 4; d++) { ulonglong2 v = gp[d]; x8[2*d] = v.x; x8[2*d+1] = v.y; }
        head_seg(x8, sw, h1);
    }
    {
        u64 x8[8];
        const ulonglong2* gp = (const ulonglong2*)(g_food + (size_t)r * 8);
        #pragma unroll
        for (int d = 0; d < 4; d++) { ulonglong2 v = gp[d]; x8[2*d] = v.x; x8[2*d+1] = v.y; }
        head_seg(x8, sw + D * HID, h1);
    }
    {
        u64 x8[8];
        const ulonglong2* gp = (const ulonglong2*)(g_other + (size_t)r * 8);
        #pragma unroll
        for (int d = 0; d < 4; d++) { ulonglong2 v = gp[d]; x8[2*d] = v.x; x8[2*d+1] = v.y; }
        head_seg(x8, sw + 2 * D * HID, h1);
    }

    u64 h2[16];
    {
        const u64* bv = (const u64*)(sw + 2592);
        #pragma unroll
        for (int j = 0; j < 16; j++) h2[j] = bv[j];
        #pragma unroll
        for (int i2 = 0; i2 < 16; i2++) {
            float a, b;
            unpack2(h1[i2], a, b);
            a = (a > 0.f) ? a : 0.01f * a;
            b = (b > 0.f) ? b : 0.01f * b;
            u64 xa = pack2(a, a);
            const ulonglong2* wa = (const ulonglong2*)(sw + 1568 + (2*i2+0) * HID);
            #pragma unroll
            for (int j = 0; j < 8; j++) {
                ulonglong2 w = wa[j];
                h2[2*j+0] = fma2(xa, w.x, h2[2*j+0]);
                h2[2*j+1] = fma2(xa, w.y, h2[2*j+1]);
            }
            u64 xb = pack2(b, b);
            const ulonglong2* wb = (const ulonglong2*)(sw + 1568 + (2*i2+1) * HID);
            #pragma unroll
            for (int j = 0; j < 8; j++) {
                ulonglong2 w = wb[j];
                h2[2*j+0] = fma2(xb, w.x, h2[2*j+0]);
                h2[2*j+1] = fma2(xb, w.y, h2[2*j+1]);
            }
        }
    }

    u64 o2 = *(const u64*)(sw + 2688);
    {
        const u64* wv = (const u64*)(sw + 2624);
        #pragma unroll
        for (int i2 = 0; i2 < 16; i2++) {
            float a, b;
            unpack2(h2[i2], a, b);
            a = (a > 0.f) ? a : 0.01f * a;
            b = (b > 0.f) ? b : 0.01f * b;
            o2 = fma2(pack2(a, a), wv[2*i2+0], o2);
            o2 = fma2(pack2(b, b), wv[2*i2+1], o2);
        }
    }
    float o0, o1;
    unpack2(o2, o0, o1);

    float2 res;
    res.x = tanhf(o0);
    res.y = tanhf(o1);
    *(float2*)(out + (size_t)2 * r) = res;
}

extern "C" void kernel_launch(void* const* d_in, const int* in_sizes, int n_in,
                              void* d_out, int out_size) {
    (void)in_sizes; (void)n_in; (void)out_size;
    const float* s    = (const float*)d_in[0];
    const int grid = BATCH / TPB;
    k_self <<<grid, TPB>>>(s, (const float*)d_in[1], (const float*)d_in[2],
                           (const float*)d_in[3], (const float*)d_in[4]);
    k_other<<<grid, TPB>>>(s, (const float*)d_in[5], (const float*)d_in[6],
                           (const float*)d_in[7], (const float*)d_in[8],
                           (const float*)d_in[13], (const float*)d_in[14]);
    k_food <<<grid, TPB>>>(s, (const float*)d_in[9], (const float*)d_in[10],
                           (const float*)d_in[11], (const float*)d_in[12],
                           (const float*)d_in[15], (const float*)d_in[16]);
    k_head <<<grid, TPB>>>((const float*)d_in[17], (const float*)d_in[18],
                           (const float*)d_in[19], (const float*)d_in[20],
                           (const float*)d_in[21], (const float*)d_in[22],
                           (float*)d_out);
}

// round 17
// speedup vs baseline: 3.5553x; 2.7118x over previous
#include <cuda_runtime.h>
#include <math.h>

#define BATCH      262144
#define IN_DIM     96
#define HID        32
#define D          16
#define LN_EPS     1e-5f
#define ATT_SCALE  0.25f        // 1/sqrt(16)

#define TPB        256
#define RPB        8            // rows (warps) per block
#define FULL       0xffffffffu

typedef unsigned long long u64;

// ---------------- packed f32x2 helpers ----------------
__device__ __forceinline__ u64 pack2(float lo, float hi) {
    u64 r; asm("mov.b64 %0, {%1, %2};" : "=l"(r) : "f"(lo), "f"(hi)); return r;
}
__device__ __forceinline__ void unpack2(u64 v, float& lo, float& hi) {
    asm("mov.b64 {%0, %1}, %2;" : "=f"(lo), "=f"(hi) : "l"(v));
}
__device__ __forceinline__ u64 fma2(u64 a, u64 b, u64 c) {
    u64 d; asm("fma.rn.f32x2 %0, %1, %2, %3;" : "=l"(d) : "l"(a), "l"(b), "l"(c)); return d;
}
__device__ __forceinline__ u64 mul2(u64 a, u64 b) {
    u64 d; asm("mul.rn.f32x2 %0, %1, %2;" : "=l"(d) : "l"(a), "l"(b)); return d;
}
__device__ __forceinline__ u64 add2(u64 a, u64 b) {
    u64 d; asm("add.rn.f32x2 %0, %1, %2;" : "=l"(d) : "l"(a), "l"(b)); return d;
}
__device__ __forceinline__ u64 relu2(u64 v) {
    float a, b; unpack2(v, a, b); return pack2(fmaxf(a, 0.f), fmaxf(b, 0.f));
}
__device__ __forceinline__ u64 shflx64(u64 v, int off) {
    return __shfl_xor_sync(FULL, v, off);
}

// ---- shared layout (float offsets) ----
// W1 groups (4x32 each, stride 136 for bank stagger): oa@0, en@136, goal(padded)@272
// b1 groups (32, stride 32): @408, @440, @472
// W2 groups (32x16, stride 520): @512, @1032, @1552
// b2 groups (16, stride 16): @2064, @2080, @2096
// LN: olng@2112 glng@2128 | olnb@2144 glnb@2160
// AW1@2176(1536) AB1@3712(32) AW2@3744(1024) AB2@4768(32) AW3@4800(64) AB3@4864(2+pad2)
// hstage@4868 (RPB*32 = 256)
#define SW_TOTAL 5124

__device__ __forceinline__ void cpyw(float* dst, const float* __restrict__ src,
                                     int n, int tid) {
    for (int i = tid; i < n; i += TPB) dst[i] = src[i];
}

__global__ void __launch_bounds__(TPB)
actor_warp_kernel(const float* __restrict__ s,
                  const float* __restrict__ enW1, const float* __restrict__ enb1,
                  const float* __restrict__ enW2, const float* __restrict__ enb2,
                  const float* __restrict__ oaW1, const float* __restrict__ oab1,
                  const float* __restrict__ oaW2, const float* __restrict__ oab2,
                  const float* __restrict__ gW1,  const float* __restrict__ gb1,
                  const float* __restrict__ gW2,  const float* __restrict__ gb2,
                  const float* __restrict__ olng, const float* __restrict__ olnb,
                  const float* __restrict__ glng, const float* __restrict__ glnb,
                  const float* __restrict__ aW1,  const float* __restrict__ ab1,
                  const float* __restrict__ aW2,  const float* __restrict__ ab2,
                  const float* __restrict__ aW3,  const float* __restrict__ ab3,
                  float* __restrict__ out) {
    __shared__ float sw[SW_TOTAL];
    const int tid = threadIdx.x;

    cpyw(sw + 0,    oaW1, 128, tid);
    cpyw(sw + 136,  enW1, 128, tid);
    cpyw(sw + 272,  gW1,  64,  tid);
    for (int i = tid; i < 64; i += TPB) sw[336 + i] = 0.f;   // goal W1 rows 2-3 = 0
    cpyw(sw + 408,  oab1, 32, tid);
    cpyw(sw + 440,  enb1, 32, tid);
    cpyw(sw + 472,  gb1,  32, tid);
    cpyw(sw + 512,  oaW2, 512, tid);
    cpyw(sw + 1032, enW2, 512, tid);
    cpyw(sw + 1552, gW2,  512, tid);
    cpyw(sw + 2064, oab2, 16, tid);
    cpyw(sw + 2080, enb2, 16, tid);
    cpyw(sw + 2096, gb2,  16, tid);
    cpyw(sw + 2112, olng, 16, tid);
    cpyw(sw + 2128, glng, 16, tid);
    cpyw(sw + 2144, olnb, 16, tid);
    cpyw(sw + 2160, glnb, 16, tid);
    cpyw(sw + 2176, aW1, 1536, tid);
    cpyw(sw + 3712, ab1, 32, tid);
    cpyw(sw + 3744, aW2, 1024, tid);
    cpyw(sw + 4768, ab2, 32, tid);
    cpyw(sw + 4800, aW3, 64, tid);
    cpyw(sw + 4864, ab3, 2, tid);
    __syncthreads();

    const int wid  = tid >> 5;
    const int lane = tid & 31;
    const size_t r = (size_t)blockIdx.x * RPB + wid;
    const float* __restrict__ row = s + r * IN_DIM;

    // lane -> encoder group: 0=other(oa), 1=self(en), 2=food(goal)
    const int g = (lane >= 16) ? 2 : ((lane == 15) ? 1 : 0);

    // ---- per-lane input gather (one 384B row per warp: 3 cache lines) ----
    float x0, x1, x2, x3;
    if (lane < 15) {
        float2 a = *(const float2*)(row + 4 + 2 * lane);
        float2 b = *(const float2*)(row + 34 + 2 * lane);
        x0 = a.x; x1 = a.y; x2 = b.x; x3 = b.y;
    } else if (lane == 15) {
        float4 a = *(const float4*)row;
        x0 = a.x; x1 = a.y; x2 = a.z; x3 = a.w;
    } else {
        float2 a = *(const float2*)(row + 64 + 2 * (lane - 16));
        x0 = a.x; x1 = a.y; x2 = 0.f; x3 = 0.f;
    }

    // ---- encoder (identical code, per-lane weight base) ----
    const float* w1 = sw + g * 136;
    const float* b1 = sw + 408 + g * 32;
    const float* w2 = sw + 512 + g * 520;
    const float* b2 = sw + 2064 + g * 16;

    u64 e8[8];
    {
        u64 h[16];
        const u64* bv = (const u64*)b1;
        #pragma unroll
        for (int j = 0; j < 16; j++) h[j] = bv[j];
        float xin[4] = {x0, x1, x2, x3};
        #pragma unroll
        for (int i = 0; i < 4; i++) {
            u64 xx = pack2(xin[i], xin[i]);
            const ulonglong2* wv = (const ulonglong2*)(w1 + i * HID);
            #pragma unroll
            for (int j = 0; j < 8; j++) {
                ulonglong2 w = wv[j];
                h[2*j+0] = fma2(xx, w.x, h[2*j+0]);
                h[2*j+1] = fma2(xx, w.y, h[2*j+1]);
            }
        }
        u64 o[8];
        const u64* b2v = (const u64*)b2;
        #pragma unroll
        for (int d = 0; d < 8; d++) o[d] = b2v[d];
        #pragma unroll
        for (int j2 = 0; j2 < 16; j2++) {
            float a, b;
            unpack2(h[j2], a, b);
            a = fmaxf(a, 0.f); b = fmaxf(b, 0.f);
            u64 ha = pack2(a, a);
            const ulonglong2* wa = (const ulonglong2*)(w2 + (2*j2+0) * D);
            #pragma unroll
            for (int d = 0; d < 4; d++) {
                ulonglong2 w = wa[d];
                o[2*d+0] = fma2(ha, w.x, o[2*d+0]);
                o[2*d+1] = fma2(ha, w.y, o[2*d+1]);
            }
            u64 hb = pack2(b, b);
            const ulonglong2* wb = (const ulonglong2*)(w2 + (2*j2+1) * D);
            #pragma unroll
            for (int d = 0; d < 4; d++) {
                ulonglong2 w = wb[d];
                o[2*d+0] = fma2(hb, w.x, o[2*d+0]);
                o[2*d+1] = fma2(hb, w.y, o[2*d+1]);
            }
        }
        #pragma unroll
        for (int d = 0; d < 8; d++) e8[d] = relu2(o[d]);
    }

    // ---- broadcast self encoding from lane 15 ----
    u64 self8[8];
    #pragma unroll
    for (int d = 0; d < 8; d++) self8[d] = __shfl_sync(FULL, e8[d], 15);

    // ---- attention score (per lane) ----
    u64 d2 = mul2(self8[0], e8[0]);
    #pragma unroll
    for (int d = 1; d < 8; d++) d2 = fma2(self8[d], e8[d], d2);
    float sa, sb;
    unpack2(d2, sa, sb);
    float sc  = (sa + sb) * ATT_SCALE;
    float scv = (lane == 15) ? -INFINITY : sc;   // self excluded from other-softmax

    // ---- softmax within each 16-lane half (offsets stay inside the half) ----
    float M = scv;
    #pragma unroll
    for (int off = 8; off >= 1; off >>= 1)
        M = fmaxf(M, __shfl_xor_sync(FULL, M, off));
    float w = __expf(scv - M);                   // lane15 -> 0
    float ssum = w;
    #pragma unroll
    for (int off = 8; off >= 1; off >>= 1)
        ssum += __shfl_xor_sync(FULL, ssum, off);

    u64 wacc[8];
    {
        u64 wpk = pack2(w, w);
        #pragma unroll
        for (int d = 0; d < 8; d++) wacc[d] = mul2(wpk, e8[d]);
        #pragma unroll
        for (int off = 8; off >= 1; off >>= 1) {
            #pragma unroll
            for (int d = 0; d < 8; d++)
                wacc[d] = add2(wacc[d], shflx64(wacc[d], off));
        }
    }
    const float inv = 1.f / ssum;

    // ---- LayerNorm + relu on this half's pool ----
    const int half = lane >> 4;                  // 0=other pool, 1=food pool
    u64 own8[8];
    {
        const float* lg = sw + 2112 + half * 16;
        const float* lb = sw + 2144 + half * 16;
        float xv[D];
        #pragma unroll
        for (int d = 0; d < 8; d++) {
            float a, b;
            unpack2(wacc[d], a, b);
            xv[2*d+0] = a * inv;
            xv[2*d+1] = b * inv;
        }
        float sum = 0.f;
        #pragma unroll
        for (int d = 0; d < D; d++) sum += xv[d];
        float mu = sum * (1.f / D);
        float v = 0.f;
        #pragma unroll
        for (int d = 0; d < D; d++) { float c = xv[d] - mu; v = fmaf(c, c, v); }
        float is = rsqrtf(v * (1.f / D) + LN_EPS);
        #pragma unroll
        for (int d = 0; d < 8; d++) {
            float ya = fmaxf(fmaf((xv[2*d+0] - mu) * is, lg[2*d+0], lb[2*d+0]), 0.f);
            float yb = fmaxf(fmaf((xv[2*d+1] - mu) * is, lg[2*d+1], lb[2*d+1]), 0.f);
            own8[d] = pack2(ya, yb);
        }
    }

    // ---- exchange pools across halves ----
    u64 foodp[8], otherp[8];
    #pragma unroll
    for (int d = 0; d < 8; d++) {
        u64 part = shflx64(own8[d], 16);
        foodp[d]  = half ? own8[d] : part;
        otherp[d] = half ? part    : own8[d];
    }

    // ---- head: lane j computes hidden unit j ----
    const float* aw1 = sw + 2176;
    float a1 = sw[3712 + lane];
    #pragma unroll
    for (int i2 = 0; i2 < 8; i2++) {
        float v0, v1;
        unpack2(self8[i2], v0, v1);
        a1 = fmaf(v0, aw1[(2*i2+0) * HID + lane], a1);
        a1 = fmaf(v1, aw1[(2*i2+1) * HID + lane], a1);
    }
    #pragma unroll
    for (int i2 = 0; i2 < 8; i2++) {
        float v0, v1;
        unpack2(foodp[i2], v0, v1);
        a1 = fmaf(v0, aw1[(16 + 2*i2+0) * HID + lane], a1);
        a1 = fmaf(v1, aw1[(16 + 2*i2+1) * HID + lane], a1);
    }
    #pragma unroll
    for (int i2 = 0; i2 < 8; i2++) {
        float v0, v1;
        unpack2(otherp[i2], v0, v1);
        a1 = fmaf(v0, aw1[(32 + 2*i2+0) * HID + lane], a1);
        a1 = fmaf(v1, aw1[(32 + 2*i2+1) * HID + lane], a1);
    }
    a1 = (a1 > 0.f) ? a1 : 0.01f * a1;

    float* hst = sw + 4868 + wid * HID;
    hst[lane] = a1;
    __syncwarp();

    float a2 = sw[4768 + lane];
    const float* aw2 = sw + 3744;
    #pragma unroll
    for (int i = 0; i < HID; i++)
        a2 = fmaf(hst[i], aw2[i * HID + lane], a2);
    a2 = (a2 > 0.f) ? a2 : 0.01f * a2;

    u64 w3 = ((const u64*)(sw + 4800))[lane];    // (W3[j][0], W3[j][1])
    u64 p = mul2(pack2(a2, a2), w3);
    #pragma unroll
    for (int off = 16; off >= 1; off >>= 1)
        p = add2(p, shflx64(p, off));

    if (lane == 0) {
        p = add2(p, *(const u64*)(sw + 4864));   // + (b3_0, b3_1)
        float o0, o1;
        unpack2(p, o0, o1);
        float2 res;
        res.x = tanhf(o0);
        res.y = tanhf(o1);
        *(float2*)(out + 2 * r) = res;
    }
}

extern "C" void kernel_launch(void* const* d_in, const int* in_sizes, int n_in,
                              void* d_out, int out_size) {
    (void)in_sizes; (void)n_in; (void)out_size;
    actor_warp_kernel<<<BATCH / RPB, TPB>>>(
        (const float*)d_in[0],
        (const float*)d_in[1],  (const float*)d_in[2],
        (const float*)d_in[3],  (const float*)d_in[4],
        (const float*)d_in[5],  (const float*)d_in[6],
        (const float*)d_in[7],  (const float*)d_in[8],
        (const float*)d_in[9],  (const float*)d_in[10],
        (const float*)d_in[11], (const float*)d_in[12],
        (const float*)d_in[13], (const float*)d_in[14],
        (const float*)d_in[15], (const float*)d_in[16],
        (const float*)d_in[17], (const float*)d_in[18],
        (const float*)d_in[19], (const float*)d_in[20],
        (const float*)d_in[21], (const float*)d_in[22],
        (float*)d_out);
}